// round 14
// baseline (speedup 1.0000x reference)
#include <cuda_runtime.h>
#include <cuda_fp16.h>
#include <cstdint>
#include <cstddef>

#define N_NODES 50000
#define DIM 256
#define N_EDGES 800000
#define N_LAYERS 5
#define W_ELEMS (N_LAYERS * 2 * DIM * DIM)
#define CSTRIDE 96   // padded-CSR slots per destination row (Poisson(16); P(deg>96) ~ 1e-40)

// ---------------- device scratch (allocation-free: .bss globals) ----------------
__device__ __half g_xa16[N_NODES * DIM];
__device__ __half g_xp16[N_NODES * DIM];
__device__ __half g_bufA0[N_NODES * DIM];
__device__ __half g_bufA1[N_NODES * DIM];
__device__ __half g_bufP0[N_NODES * DIM];
__device__ __half g_bufP1[N_NODES * DIM];
__device__ __half g_aggA[N_NODES * DIM];
__device__ __half g_aggP[N_NODES * DIM];
__device__ __half g_hWl[W_ELEMS];
__device__ __half g_hWr[W_ELEMS];
__device__ int    g_cntA[N_NODES];
__device__ int    g_cntP[N_NODES];
__device__ int    g_csrA[(size_t)N_NODES * CSTRIDE];
__device__ int    g_csrP[(size_t)N_NODES * CSTRIDE];

// ---------------- second stream + events, created once ----------------
struct AuxStream {
    cudaStream_t s;
    cudaEvent_t fork, join;
    AuxStream() {
        cudaStreamCreateWithFlags(&s, cudaStreamNonBlocking);
        cudaEventCreateWithFlags(&fork, cudaEventDisableTiming);
        cudaEventCreateWithFlags(&join, cudaEventDisableTiming);
    }
};
static AuxStream g_aux;

// ---------------- fp32 -> fp16 convert ----------------
__global__ void cvt2h_kernel(const float* __restrict__ a, const float* __restrict__ b,
                             __half* __restrict__ ah, __half* __restrict__ bh, int n4) {
    int i = blockIdx.x * blockDim.x + threadIdx.x;
    if (i < n4) {
        float4 va = reinterpret_cast<const float4*>(a)[i];
        float4 vb = reinterpret_cast<const float4*>(b)[i];
        reinterpret_cast<__half2*>(ah)[i * 2]     = __floats2half2_rn(va.x, va.y);
        reinterpret_cast<__half2*>(ah)[i * 2 + 1] = __floats2half2_rn(va.z, va.w);
        reinterpret_cast<__half2*>(bh)[i * 2]     = __floats2half2_rn(vb.x, vb.y);
        reinterpret_cast<__half2*>(bh)[i * 2 + 1] = __floats2half2_rn(vb.z, vb.w);
    }
}

// ---------------- padded-CSR build: one pass, both directions (grid.y=2) ----------------
__global__ void fillpad_kernel(const int* __restrict__ eap, int* __restrict__ cntP,
                               int* __restrict__ csrP,
                               const int* __restrict__ epa, int* __restrict__ cntA,
                               int* __restrict__ csrA, int E) {
    int e = blockIdx.x * blockDim.x + threadIdx.x;
    if (e < E) {
        if (blockIdx.y == 0) {
            int d = eap[E + e];
            int slot = atomicAdd(&cntP[d], 1);
            if (slot < CSTRIDE) csrP[(size_t)d * CSTRIDE + slot] = eap[e];
        } else {
            int d = epa[E + e];
            int slot = atomicAdd(&cntA[d], 1);
            if (slot < CSTRIDE) csrA[(size_t)d * CSTRIDE + slot] = epa[e];
        }
    }
}

// ---------------- gather (fp16 rows; ONE direction; padded CSR; 2-edge unroll) ----------------
__global__ void gather1_kernel(const __half* __restrict__ x, const int* __restrict__ cnt,
                               const int* __restrict__ csr, __half* __restrict__ agg, int n) {
    int row = blockIdx.x * (blockDim.x >> 5) + (threadIdx.x >> 5);
    if (row >= n) return;
    const int lane = threadIdx.x & 31;
    const int deg = cnt[row];
    const int* lst = csr + (size_t)row * CSTRIDE;

    float s[8] = {0.f, 0.f, 0.f, 0.f, 0.f, 0.f, 0.f, 0.f};
    int e = 0;
    for (; e + 1 < deg; e += 2) {
        int i0 = lst[e], i1 = lst[e + 1];
        uint4 v0 = reinterpret_cast<const uint4*>(x + (size_t)i0 * DIM)[lane];
        uint4 v1 = reinterpret_cast<const uint4*>(x + (size_t)i1 * DIM)[lane];
        const __half2* h0 = reinterpret_cast<const __half2*>(&v0);
        const __half2* h1 = reinterpret_cast<const __half2*>(&v1);
#pragma unroll
        for (int j = 0; j < 4; j++) {
            float2 f0 = __half22float2(h0[j]);
            float2 f1 = __half22float2(h1[j]);
            s[j * 2]     += f0.x + f1.x;
            s[j * 2 + 1] += f0.y + f1.y;
        }
    }
    if (e < deg) {
        uint4 v0 = reinterpret_cast<const uint4*>(x + (size_t)lst[e] * DIM)[lane];
        const __half2* h0 = reinterpret_cast<const __half2*>(&v0);
#pragma unroll
        for (int j = 0; j < 4; j++) {
            float2 f0 = __half22float2(h0[j]);
            s[j * 2]     += f0.x;
            s[j * 2 + 1] += f0.y;
        }
    }
    const float inv = 1.0f / fmaxf((float)deg, 1.0f);
    uint4 o;
    __half2* ho = reinterpret_cast<__half2*>(&o);
#pragma unroll
    for (int j = 0; j < 4; j++)
        ho[j] = __floats2half2_rn(s[j * 2] * inv, s[j * 2 + 1] * inv);
    reinterpret_cast<uint4*>(agg + (size_t)row * DIM)[lane] = o;
}

// ---------------- fp16 tensor-core fused dual-input GEMM (ONE direction) ----------------
// out = agg @ Wl^T + self @ Wr^T + b (fp32 accum). m16n8k16, BM=128, BN=128, BK=32,
// 3-stage cp.async, XOR-swizzled smem, LDSM.x4 fragments, 8 warps, warp tile 32x64.

__device__ __forceinline__ void cp_async16(void* smem, const void* gmem, bool pred) {
    uint32_t s = (uint32_t)__cvta_generic_to_shared(smem);
    int sz = pred ? 16 : 0;
    asm volatile("cp.async.cg.shared.global [%0], [%1], 16, %2;"
                 :: "r"(s), "l"(gmem), "r"(sz));
}

#define LDSM_X4(r0, r1, r2, r3, addr)                                     \
    asm volatile("ldmatrix.sync.aligned.m8n8.x4.shared.b16 "              \
                 "{%0,%1,%2,%3}, [%4];"                                   \
                 : "=r"(r0), "=r"(r1), "=r"(r2), "=r"(r3) : "r"(addr))

#define STG_H (128 * 32)   // halfs per tile per stage (8KB)

__global__ __launch_bounds__(256, 2)
void gemm1_kernel(const __half* __restrict__ Aagg, const __half* __restrict__ Aself,
                  const __half* __restrict__ Wl, const __half* __restrict__ Wr,
                  const float* __restrict__ bias,
                  __half* __restrict__ outH, float* __restrict__ outF, int M) {
    extern __shared__ __half sm[];
    __half* As = sm;                 // [3][128][32] XOR-swizzled
    __half* Bs = sm + 3 * STG_H;

    const int bm = blockIdx.y * 128;
    const int bn = blockIdx.x * 128;
    const int t = threadIdx.x;
    const int wid = t >> 5;
    const int lane = t & 31;
    const int wm = wid & 3;
    const int wn = wid >> 2;
    const int gid = lane >> 2;
    const int tig = lane & 3;

    const uint32_t smem_u32 = (uint32_t)__cvta_generic_to_shared(sm);
    const uint32_t baseA = smem_u32;
    const uint32_t baseB = smem_u32 + 3 * STG_H * 2;

    const int matq = lane >> 3;
    const int rq = lane & 7;
    const int kselA = matq >> 1;
    uint32_t rowA[2]; int swA[2];
#pragma unroll
    for (int mi = 0; mi < 2; mi++) {
        int row = wm * 32 + mi * 16 + (matq & 1) * 8 + rq;
        rowA[mi] = row * 64;
        swA[mi] = (row >> 1) & 3;
    }
    const int kselB = matq & 1;
    uint32_t rowB[4]; int swB[4];
#pragma unroll
    for (int j = 0; j < 4; j++) {
        int ni = 2 * j + (matq >> 1);
        int row = wn * 64 + ni * 8 + rq;
        rowB[j] = row * 64;
        swB[j] = (row >> 1) & 3;
    }

    float acc[2][8][4];
#pragma unroll
    for (int mi = 0; mi < 2; mi++)
#pragma unroll
        for (int ni = 0; ni < 8; ni++)
#pragma unroll
            for (int j = 0; j < 4; j++) acc[mi][ni][j] = 0.0f;

    auto load_tile = [&](int stage, int kt) {
        const int phase = kt >> 3;
        const int kloc = (kt & 7) << 5;
        const __half* Ap = phase ? Aself : Aagg;
        const __half* Bp = phase ? Wr : Wl;
        __half* as = As + stage * STG_H;
        __half* bs = Bs + stage * STG_H;
#pragma unroll
        for (int i = 0; i < 2; i++) {
            int c = t + i * 256;
            int row = c >> 2;
            int seg = c & 3;
            int segp = seg ^ ((row >> 1) & 3);
            int gr = bm + row;
            cp_async16(as + row * 32 + segp * 8,
                       Ap + (size_t)gr * DIM + kloc + seg * 8, gr < M);
            cp_async16(bs + row * 32 + segp * 8,
                       Bp + (size_t)(bn + row) * DIM + kloc + seg * 8, true);
        }
        asm volatile("cp.async.commit_group;" ::: "memory");
    };

    load_tile(0, 0);
    load_tile(1, 1);

#pragma unroll 1
    for (int kt = 0; kt < 16; kt++) {
        const int s = kt % 3;
        if (kt < 15)
            asm volatile("cp.async.wait_group 1;" ::: "memory");
        else
            asm volatile("cp.async.wait_group 0;" ::: "memory");   // final tile must be fully resident
        __syncthreads();
        if (kt + 2 < 16) load_tile((kt + 2) % 3, kt + 2);

        const uint32_t sA = baseA + s * (STG_H * 2);
        const uint32_t sB = baseB + s * (STG_H * 2);

#pragma unroll
        for (int ks = 0; ks < 2; ks++) {
            const int gA = ks * 2;
            uint32_t aR[2][4];
#pragma unroll
            for (int mi = 0; mi < 2; mi++) {
                uint32_t addr = sA + rowA[mi] + (uint32_t)(((gA + kselA) ^ swA[mi]) << 4);
                LDSM_X4(aR[mi][0], aR[mi][1], aR[mi][2], aR[mi][3], addr);
            }
            uint32_t bR[8][2];
#pragma unroll
            for (int j = 0; j < 4; j++) {
                uint32_t addr = sB + rowB[j] + (uint32_t)(((gA + kselB) ^ swB[j]) << 4);
                LDSM_X4(bR[2 * j][0], bR[2 * j][1], bR[2 * j + 1][0], bR[2 * j + 1][1], addr);
            }
#pragma unroll
            for (int mi = 0; mi < 2; mi++)
#pragma unroll
                for (int ni = 0; ni < 8; ni++) {
                    asm volatile(
                        "mma.sync.aligned.m16n8k16.row.col.f32.f16.f16.f32 "
                        "{%0,%1,%2,%3}, {%4,%5,%6,%7}, {%8,%9}, {%0,%1,%2,%3};"
                        : "+f"(acc[mi][ni][0]), "+f"(acc[mi][ni][1]),
                          "+f"(acc[mi][ni][2]), "+f"(acc[mi][ni][3])
                        : "r"(aR[mi][0]), "r"(aR[mi][1]), "r"(aR[mi][2]), "r"(aR[mi][3]),
                          "r"(bR[ni][0]), "r"(bR[ni][1]));
                }
        }
    }

#pragma unroll
    for (int ni = 0; ni < 8; ni++) {
        int col = bn + wn * 64 + ni * 8 + 2 * tig;
        float bx = bias[col], by = bias[col + 1];
#pragma unroll
        for (int mi = 0; mi < 2; mi++) {
            int r0 = bm + wm * 32 + mi * 16 + gid;
            float ox0 = acc[mi][ni][0] + bx, oy0 = acc[mi][ni][1] + by;
            float ox1 = acc[mi][ni][2] + bx, oy1 = acc[mi][ni][3] + by;
            if (outH) {
                if (r0 < M)
                    *reinterpret_cast<__half2*>(outH + (size_t)r0 * DIM + col) =
                        __floats2half2_rn(ox0, oy0);
                if (r0 + 8 < M)
                    *reinterpret_cast<__half2*>(outH + (size_t)(r0 + 8) * DIM + col) =
                        __floats2half2_rn(ox1, oy1);
            } else {
                if (r0 < M)
                    *reinterpret_cast<float2*>(outF + (size_t)r0 * DIM + col) =
                        make_float2(ox0, oy0);
                if (r0 + 8 < M)
                    *reinterpret_cast<float2*>(outF + (size_t)(r0 + 8) * DIM + col) =
                        make_float2(ox1, oy1);
            }
        }
    }
}

// ---------------- L2 normalize + ReLU (fp16, ONE matrix) ----------------
__global__ void norm_relu1_kernel(__half* __restrict__ x, int n) {
    int row = blockIdx.x * (blockDim.x >> 5) + (threadIdx.x >> 5);
    if (row >= n) return;
    int lane = threadIdx.x & 31;
    uint4 v = reinterpret_cast<uint4*>(x + (size_t)row * DIM)[lane];
    __half2* h = reinterpret_cast<__half2*>(&v);
    float f[8];
    float s = 0.f;
#pragma unroll
    for (int j = 0; j < 4; j++) {
        float2 p = __half22float2(h[j]);
        f[j * 2] = p.x; f[j * 2 + 1] = p.y;
        s += p.x * p.x + p.y * p.y;
    }
#pragma unroll
    for (int o = 16; o; o >>= 1) s += __shfl_xor_sync(0xFFFFFFFFu, s, o);
    float inv = 1.0f / fmaxf(sqrtf(s), 1e-12f);
    uint4 ov;
    __half2* ho = reinterpret_cast<__half2*>(&ov);
#pragma unroll
    for (int j = 0; j < 4; j++)
        ho[j] = __floats2half2_rn(fmaxf(f[j * 2] * inv, 0.f), fmaxf(f[j * 2 + 1] * inv, 0.f));
    reinterpret_cast<uint4*>(x + (size_t)row * DIM)[lane] = ov;
}

// ---------------- host orchestration ----------------
extern "C" void kernel_launch(void* const* d_in, const int* in_sizes, int n_in,
                              void* d_out, int out_size) {
    (void)in_sizes; (void)n_in; (void)out_size;
    const float* xa_in = (const float*)d_in[0];
    const float* xp_in = (const float*)d_in[1];
    const float* Wl    = (const float*)d_in[2];
    const float* bl    = (const float*)d_in[3];
    const float* Wr    = (const float*)d_in[4];
    const int*   e_ap  = (const int*)d_in[5];
    const int*   e_pa  = (const int*)d_in[6];
    float* out = (float*)d_out;

    __half *xa16, *xp16, *bufA[2], *bufP[2], *aggA, *aggP, *hWl, *hWr;
    int *cntA, *cntP, *csrA, *csrP;
    cudaGetSymbolAddress((void**)&xa16, g_xa16);
    cudaGetSymbolAddress((void**)&xp16, g_xp16);
    cudaGetSymbolAddress((void**)&bufA[0], g_bufA0);
    cudaGetSymbolAddress((void**)&bufA[1], g_bufA1);
    cudaGetSymbolAddress((void**)&bufP[0], g_bufP0);
    cudaGetSymbolAddress((void**)&bufP[1], g_bufP1);
    cudaGetSymbolAddress((void**)&aggA, g_aggA);
    cudaGetSymbolAddress((void**)&aggP, g_aggP);
    cudaGetSymbolAddress((void**)&hWl, g_hWl);
    cudaGetSymbolAddress((void**)&hWr, g_hWr);
    cudaGetSymbolAddress((void**)&cntA, g_cntA);
    cudaGetSymbolAddress((void**)&cntP, g_cntP);
    cudaGetSymbolAddress((void**)&csrA, g_csrA);
    cudaGetSymbolAddress((void**)&csrP, g_csrP);

    static bool attr_set = false;
    if (!attr_set) {
        cudaFuncSetAttribute(gemm1_kernel, cudaFuncAttributeMaxDynamicSharedMemorySize,
                             6 * STG_H * (int)sizeof(__half));
        attr_set = true;
    }

    cudaStream_t sx = g_aux.s;

    // ---- fork: converts on default stream, padded-CSR build on aux stream ----
    cudaEventRecord(g_aux.fork, 0);
    cudaStreamWaitEvent(sx, g_aux.fork, 0);

    cvt2h_kernel<<<(N_NODES * DIM / 4 + 255) / 256, 256>>>(xa_in, xp_in, xa16, xp16,
                                                           N_NODES * DIM / 4);
    cvt2h_kernel<<<(W_ELEMS / 4 + 255) / 256, 256>>>(Wl, Wr, hWl, hWr, W_ELEMS / 4);

    cudaMemsetAsync(cntA, 0, N_NODES * sizeof(int), sx);
    cudaMemsetAsync(cntP, 0, N_NODES * sizeof(int), sx);
    {
        dim3 g((N_EDGES + 255) / 256, 2);
        fillpad_kernel<<<g, 256, 0, sx>>>(e_ap, cntP, csrP, e_pa, cntA, csrA, N_EDGES);
    }

    cudaEventRecord(g_aux.join, sx);
    cudaStreamWaitEvent(0, g_aux.join, 0);

    const __half* inA = xa16;
    const __half* inP = xp16;

    dim3 gGrid(2, (N_NODES + 127) / 128);    // (2, 391) per direction
    int wBlocks = (N_NODES + 7) / 8;
    const int smemBytes = 6 * STG_H * (int)sizeof(__half);   // 48KB

    for (int l = 0; l < N_LAYERS; l++) {
        const bool last = (l == N_LAYERS - 1);
        __half* outA = last ? nullptr : bufA[l & 1];
        __half* outP = last ? nullptr : bufP[l & 1];
        float* outA_f = last ? out : nullptr;
        float* outP_f = last ? out + (size_t)N_NODES * DIM : nullptr;

        const __half* wl_p = hWl + ((size_t)l * 2 + 0) * DIM * DIM;
        const __half* wr_p = hWr + ((size_t)l * 2 + 0) * DIM * DIM;
        const float*  bl_p = bl + ((size_t)l * 2 + 0) * DIM;
        const __half* wl_a = hWl + ((size_t)l * 2 + 1) * DIM * DIM;
        const __half* wr_a = hWr + ((size_t)l * 2 + 1) * DIM * DIM;
        const float*  bl_a = bl + ((size_t)l * 2 + 1) * DIM;

        // fork the two independent direction chains
        cudaEventRecord(g_aux.fork, 0);
        cudaStreamWaitEvent(sx, g_aux.fork, 0);

        // chain P (default stream)
        gather1_kernel<<<wBlocks, 256>>>(inA, cntP, csrP, aggP, N_NODES);
        gemm1_kernel<<<gGrid, 256, smemBytes>>>(aggP, inP, wl_p, wr_p, bl_p,
                                                outP, outP_f, N_NODES);
        if (!last) norm_relu1_kernel<<<wBlocks, 256>>>(outP, N_NODES);

        // chain A (aux stream)
        gather1_kernel<<<wBlocks, 256, 0, sx>>>(inP, cntA, csrA, aggA, N_NODES);
        gemm1_kernel<<<gGrid, 256, smemBytes, sx>>>(aggA, inA, wl_a, wr_a, bl_a,
                                                    outA, outA_f, N_NODES);
        if (!last) norm_relu1_kernel<<<wBlocks, 256, 0, sx>>>(outA, N_NODES);

        // join before next layer (cross-direction dependency)
        cudaEventRecord(g_aux.join, sx);
        cudaStreamWaitEvent(0, g_aux.join, 0);

        inA = outA;
        inP = outP;
    }
}

// round 15
// speedup vs baseline: 1.0452x; 1.0452x over previous
#include <cuda_runtime.h>
#include <cuda_fp16.h>
#include <cstdint>
#include <cstddef>

#define N_NODES 50000
#define DIM 256
#define N_EDGES 800000
#define N_LAYERS 5
#define W_ELEMS (N_LAYERS * 2 * DIM * DIM)

#define SCHUNK 512
#define SNB ((N_NODES + SCHUNK - 1) / SCHUNK)   // 98

// ---------------- device scratch (allocation-free: .bss globals) ----------------
__device__ __half g_xa16[N_NODES * DIM];
__device__ __half g_xp16[N_NODES * DIM];
__device__ __half g_bufA0[N_NODES * DIM];
__device__ __half g_bufA1[N_NODES * DIM];
__device__ __half g_bufP0[N_NODES * DIM];
__device__ __half g_bufP1[N_NODES * DIM];
__device__ __half g_aggA[N_NODES * DIM];
__device__ __half g_aggP[N_NODES * DIM];
__device__ __half g_hWl[W_ELEMS];
__device__ __half g_hWr[W_ELEMS];
__device__ int    g_degA[N_NODES];
__device__ int    g_degP[N_NODES];
__device__ int    g_offA[N_NODES + 1];
__device__ int    g_offP[N_NODES + 1];
__device__ int    g_curA[N_NODES];
__device__ int    g_curP[N_NODES];
__device__ int    g_csrA[N_EDGES];
__device__ int    g_csrP[N_EDGES];
__device__ int    g_part[2][SNB];

// ---------------- second stream + events, created once ----------------
struct AuxStream {
    cudaStream_t s;
    cudaEvent_t fork, join;
    AuxStream() {
        cudaStreamCreateWithFlags(&s, cudaStreamNonBlocking);
        cudaEventCreateWithFlags(&fork, cudaEventDisableTiming);
        cudaEventCreateWithFlags(&join, cudaEventDisableTiming);
    }
};
static AuxStream g_aux;

// ---------------- fp32 -> fp16 convert: features + weights in ONE launch ----------------
__global__ void cvt_all_kernel(const float* __restrict__ xa, const float* __restrict__ xp,
                               __half* __restrict__ xah, __half* __restrict__ xph,
                               const float* __restrict__ wl, const float* __restrict__ wr,
                               __half* __restrict__ wlh, __half* __restrict__ wrh,
                               int n4f, int n4w) {
    int i = blockIdx.x * blockDim.x + threadIdx.x;
    if (i < n4f) {
        float4 va = reinterpret_cast<const float4*>(xa)[i];
        float4 vb = reinterpret_cast<const float4*>(xp)[i];
        reinterpret_cast<__half2*>(xah)[i * 2]     = __floats2half2_rn(va.x, va.y);
        reinterpret_cast<__half2*>(xah)[i * 2 + 1] = __floats2half2_rn(va.z, va.w);
        reinterpret_cast<__half2*>(xph)[i * 2]     = __floats2half2_rn(vb.x, vb.y);
        reinterpret_cast<__half2*>(xph)[i * 2 + 1] = __floats2half2_rn(vb.z, vb.w);
    }
    if (i < n4w) {
        float4 va = reinterpret_cast<const float4*>(wl)[i];
        float4 vb = reinterpret_cast<const float4*>(wr)[i];
        reinterpret_cast<__half2*>(wlh)[i * 2]     = __floats2half2_rn(va.x, va.y);
        reinterpret_cast<__half2*>(wlh)[i * 2 + 1] = __floats2half2_rn(va.z, va.w);
        reinterpret_cast<__half2*>(wrh)[i * 2]     = __floats2half2_rn(vb.x, vb.y);
        reinterpret_cast<__half2*>(wrh)[i * 2 + 1] = __floats2half2_rn(vb.z, vb.w);
    }
}

// ---------------- CSR build ----------------
__global__ void deg2_kernel(const int* __restrict__ dstP, int* __restrict__ degP,
                            const int* __restrict__ dstA, int* __restrict__ degA, int E) {
    int e = blockIdx.x * blockDim.x + threadIdx.x;
    if (e < E) {
        if (blockIdx.y == 0) atomicAdd(&degP[dstP[e]], 1);
        else                 atomicAdd(&degA[dstA[e]], 1);
    }
}

__global__ void scan_p1(const int* __restrict__ dP, const int* __restrict__ dA, int n) {
    const int* deg = blockIdx.y ? dA : dP;
    const int tid = threadIdx.x;                 // 256
    int i0 = blockIdx.x * SCHUNK + tid * 2;
    int v = 0;
    if (i0 < n)     v += deg[i0];
    if (i0 + 1 < n) v += deg[i0 + 1];
    __shared__ int ws[8];
#pragma unroll
    for (int o = 16; o; o >>= 1) v += __shfl_xor_sync(0xFFFFFFFFu, v, o);
    if ((tid & 31) == 0) ws[tid >> 5] = v;
    __syncthreads();
    if (tid == 0) {
        int s = 0;
#pragma unroll
        for (int w = 0; w < 8; w++) s += ws[w];
        g_part[blockIdx.y][blockIdx.x] = s;
    }
}

__global__ void scan_p2(int* __restrict__ offP, int* __restrict__ offA, int n) {
    const int dir = blockIdx.x;
    int* off = dir ? offA : offP;
    const int tid = threadIdx.x;                 // 128
    int v = (tid < SNB) ? g_part[dir][tid] : 0;
    __shared__ int ws[4];
    int x = v;
    const int lane = tid & 31, wid = tid >> 5;
#pragma unroll
    for (int o = 1; o < 32; o <<= 1) {
        int y = __shfl_up_sync(0xFFFFFFFFu, x, o);
        if (lane >= o) x += y;
    }
    if (lane == 31) ws[wid] = x;
    __syncthreads();
    if (tid < 4) {
        int w = ws[tid];
#pragma unroll
        for (int o = 1; o < 4; o <<= 1) {
            int y = __shfl_up_sync(0xFu, w, o);
            if (tid >= o) w += y;
        }
        ws[tid] = w;
    }
    __syncthreads();
    int incl = x + (wid ? ws[wid - 1] : 0);
    if (tid < SNB) g_part[dir][tid] = incl - v;
    if (tid == 127) off[n] = incl;
}

__global__ void scan_p3(const int* __restrict__ dP, const int* __restrict__ dA,
                        int* __restrict__ offP, int* __restrict__ curP,
                        int* __restrict__ offA, int* __restrict__ curA, int n) {
    const int dir = blockIdx.y;
    const int* deg = dir ? dA : dP;
    int* off = dir ? offA : offP;
    int* cur = dir ? curA : curP;
    const int tid = threadIdx.x;                 // 256
    const int base = g_part[dir][blockIdx.x];
    int i0 = blockIdx.x * SCHUNK + tid * 2;
    int v0 = (i0 < n) ? deg[i0] : 0;
    int v1 = (i0 + 1 < n) ? deg[i0 + 1] : 0;
    int sum = v0 + v1;

    __shared__ int ws[8];
    int x = sum;
    const int lane = tid & 31, wid = tid >> 5;
#pragma unroll
    for (int o = 1; o < 32; o <<= 1) {
        int y = __shfl_up_sync(0xFFFFFFFFu, x, o);
        if (lane >= o) x += y;
    }
    if (lane == 31) ws[wid] = x;
    __syncthreads();
    if (tid < 8) {
        int w = ws[tid];
#pragma unroll
        for (int o = 1; o < 8; o <<= 1) {
            int y = __shfl_up_sync(0xFFu, w, o);
            if (tid >= o) w += y;
        }
        ws[tid] = w;
    }
    __syncthreads();
    int excl = x - sum + (wid ? ws[wid - 1] : 0);
    int p = base + excl;
    if (i0 < n)     { off[i0] = p;          cur[i0] = p; }
    if (i0 + 1 < n) { off[i0 + 1] = p + v0; cur[i0 + 1] = p + v0; }
}

__global__ void fill2_kernel(const int* __restrict__ eap, int* __restrict__ curP, int* __restrict__ csrP,
                             const int* __restrict__ epa, int* __restrict__ curA, int* __restrict__ csrA,
                             int E) {
    int e = blockIdx.x * blockDim.x + threadIdx.x;
    if (e < E) {
        if (blockIdx.y == 0) {
            int slot = atomicAdd(&curP[eap[E + e]], 1);
            csrP[slot] = eap[e];
        } else {
            int slot = atomicAdd(&curA[epa[E + e]], 1);
            csrA[slot] = epa[e];
        }
    }
}

// ---------------- gather (fp16 rows; ONE direction; 2-edge unroll, 40 regs) ----------------
__global__ void gather1_kernel(const __half* __restrict__ x, const int* __restrict__ off,
                               const int* __restrict__ csr, __half* __restrict__ agg, int n) {
    int row = blockIdx.x * (blockDim.x >> 5) + (threadIdx.x >> 5);
    if (row >= n) return;
    const int lane = threadIdx.x & 31;
    const int beg = off[row], end = off[row + 1];

    float s[8] = {0.f, 0.f, 0.f, 0.f, 0.f, 0.f, 0.f, 0.f};
    int e = beg;
    for (; e + 1 < end; e += 2) {
        int i0 = csr[e], i1 = csr[e + 1];
        uint4 v0 = reinterpret_cast<const uint4*>(x + (size_t)i0 * DIM)[lane];
        uint4 v1 = reinterpret_cast<const uint4*>(x + (size_t)i1 * DIM)[lane];
        const __half2* h0 = reinterpret_cast<const __half2*>(&v0);
        const __half2* h1 = reinterpret_cast<const __half2*>(&v1);
#pragma unroll
        for (int j = 0; j < 4; j++) {
            float2 f0 = __half22float2(h0[j]);
            float2 f1 = __half22float2(h1[j]);
            s[j * 2]     += f0.x + f1.x;
            s[j * 2 + 1] += f0.y + f1.y;
        }
    }
    if (e < end) {
        uint4 v0 = reinterpret_cast<const uint4*>(x + (size_t)csr[e] * DIM)[lane];
        const __half2* h0 = reinterpret_cast<const __half2*>(&v0);
#pragma unroll
        for (int j = 0; j < 4; j++) {
            float2 f0 = __half22float2(h0[j]);
            s[j * 2]     += f0.x;
            s[j * 2 + 1] += f0.y;
        }
    }
    const float inv = 1.0f / fmaxf((float)(end - beg), 1.0f);
    uint4 o;
    __half2* ho = reinterpret_cast<__half2*>(&o);
#pragma unroll
    for (int j = 0; j < 4; j++)
        ho[j] = __floats2half2_rn(s[j * 2] * inv, s[j * 2 + 1] * inv);
    reinterpret_cast<uint4*>(agg + (size_t)row * DIM)[lane] = o;
}

// ---------------- fp16 tensor-core fused dual-input GEMM (ONE direction) ----------------
// out = agg @ Wl^T + self @ Wr^T + b (fp32 accum). m16n8k16, BM=128, BN=128, BK=32,
// 3-stage cp.async, XOR-swizzled smem, LDSM.x4 fragments, 8 warps, warp tile 32x64.

__device__ __forceinline__ void cp_async16(void* smem, const void* gmem, bool pred) {
    uint32_t s = (uint32_t)__cvta_generic_to_shared(smem);
    int sz = pred ? 16 : 0;
    asm volatile("cp.async.cg.shared.global [%0], [%1], 16, %2;"
                 :: "r"(s), "l"(gmem), "r"(sz));
}

#define LDSM_X4(r0, r1, r2, r3, addr)                                     \
    asm volatile("ldmatrix.sync.aligned.m8n8.x4.shared.b16 "              \
                 "{%0,%1,%2,%3}, [%4];"                                   \
                 : "=r"(r0), "=r"(r1), "=r"(r2), "=r"(r3) : "r"(addr))

#define STG_H (128 * 32)   // halfs per tile per stage (8KB)

__global__ __launch_bounds__(256, 2)
void gemm1_kernel(const __half* __restrict__ Aagg, const __half* __restrict__ Aself,
                  const __half* __restrict__ Wl, const __half* __restrict__ Wr,
                  const float* __restrict__ bias,
                  __half* __restrict__ outH, float* __restrict__ outF, int M) {
    extern __shared__ __half sm[];
    __half* As = sm;                 // [3][128][32] XOR-swizzled
    __half* Bs = sm + 3 * STG_H;

    const int bm = blockIdx.y * 128;
    const int bn = blockIdx.x * 128;
    const int t = threadIdx.x;
    const int wid = t >> 5;
    const int lane = t & 31;
    const int wm = wid & 3;
    const int wn = wid >> 2;
    const int gid = lane >> 2;
    const int tig = lane & 3;

    const uint32_t smem_u32 = (uint32_t)__cvta_generic_to_shared(sm);
    const uint32_t baseA = smem_u32;
    const uint32_t baseB = smem_u32 + 3 * STG_H * 2;

    const int matq = lane >> 3;
    const int rq = lane & 7;
    const int kselA = matq >> 1;
    uint32_t rowA[2]; int swA[2];
#pragma unroll
    for (int mi = 0; mi < 2; mi++) {
        int row = wm * 32 + mi * 16 + (matq & 1) * 8 + rq;
        rowA[mi] = row * 64;
        swA[mi] = (row >> 1) & 3;
    }
    const int kselB = matq & 1;
    uint32_t rowB[4]; int swB[4];
#pragma unroll
    for (int j = 0; j < 4; j++) {
        int ni = 2 * j + (matq >> 1);
        int row = wn * 64 + ni * 8 + rq;
        rowB[j] = row * 64;
        swB[j] = (row >> 1) & 3;
    }

    float acc[2][8][4];
#pragma unroll
    for (int mi = 0; mi < 2; mi++)
#pragma unroll
        for (int ni = 0; ni < 8; ni++)
#pragma unroll
            for (int j = 0; j < 4; j++) acc[mi][ni][j] = 0.0f;

    auto load_tile = [&](int stage, int kt) {
        const int phase = kt >> 3;
        const int kloc = (kt & 7) << 5;
        const __half* Ap = phase ? Aself : Aagg;
        const __half* Bp = phase ? Wr : Wl;
        __half* as = As + stage * STG_H;
        __half* bs = Bs + stage * STG_H;
#pragma unroll
        for (int i = 0; i < 2; i++) {
            int c = t + i * 256;
            int row = c >> 2;
            int seg = c & 3;
            int segp = seg ^ ((row >> 1) & 3);
            int gr = bm + row;
            cp_async16(as + row * 32 + segp * 8,
                       Ap + (size_t)gr * DIM + kloc + seg * 8, gr < M);
            cp_async16(bs + row * 32 + segp * 8,
                       Bp + (size_t)(bn + row) * DIM + kloc + seg * 8, true);
        }
        asm volatile("cp.async.commit_group;" ::: "memory");
    };

    load_tile(0, 0);
    load_tile(1, 1);

#pragma unroll 1
    for (int kt = 0; kt < 16; kt++) {
        const int s = kt % 3;
        if (kt < 15)
            asm volatile("cp.async.wait_group 1;" ::: "memory");
        else
            asm volatile("cp.async.wait_group 0;" ::: "memory");   // final tile must be fully resident
        __syncthreads();
        if (kt + 2 < 16) load_tile((kt + 2) % 3, kt + 2);

        const uint32_t sA = baseA + s * (STG_H * 2);
        const uint32_t sB = baseB + s * (STG_H * 2);

#pragma unroll
        for (int ks = 0; ks < 2; ks++) {
            const int gA = ks * 2;
            uint32_t aR[2][4];
#pragma unroll
            for (int mi = 0; mi < 2; mi++) {
                uint32_t addr = sA + rowA[mi] + (uint32_t)(((gA + kselA) ^ swA[mi]) << 4);
                LDSM_X4(aR[mi][0], aR[mi][1], aR[mi][2], aR[mi][3], addr);
            }
            uint32_t bR[8][2];
#pragma unroll
            for (int j = 0; j < 4; j++) {
                uint32_t addr = sB + rowB[j] + (uint32_t)(((gA + kselB) ^ swB[j]) << 4);
                LDSM_X4(bR[2 * j][0], bR[2 * j][1], bR[2 * j + 1][0], bR[2 * j + 1][1], addr);
            }
#pragma unroll
            for (int mi = 0; mi < 2; mi++)
#pragma unroll
                for (int ni = 0; ni < 8; ni++) {
                    asm volatile(
                        "mma.sync.aligned.m16n8k16.row.col.f32.f16.f16.f32 "
                        "{%0,%1,%2,%3}, {%4,%5,%6,%7}, {%8,%9}, {%0,%1,%2,%3};"
                        : "+f"(acc[mi][ni][0]), "+f"(acc[mi][ni][1]),
                          "+f"(acc[mi][ni][2]), "+f"(acc[mi][ni][3])
                        : "r"(aR[mi][0]), "r"(aR[mi][1]), "r"(aR[mi][2]), "r"(aR[mi][3]),
                          "r"(bR[ni][0]), "r"(bR[ni][1]));
                }
        }
    }

#pragma unroll
    for (int ni = 0; ni < 8; ni++) {
        int col = bn + wn * 64 + ni * 8 + 2 * tig;
        float bx = bias[col], by = bias[col + 1];
#pragma unroll
        for (int mi = 0; mi < 2; mi++) {
            int r0 = bm + wm * 32 + mi * 16 + gid;
            float ox0 = acc[mi][ni][0] + bx, oy0 = acc[mi][ni][1] + by;
            float ox1 = acc[mi][ni][2] + bx, oy1 = acc[mi][ni][3] + by;
            if (outH) {
                if (r0 < M)
                    *reinterpret_cast<__half2*>(outH + (size_t)r0 * DIM + col) =
                        __floats2half2_rn(ox0, oy0);
                if (r0 + 8 < M)
                    *reinterpret_cast<__half2*>(outH + (size_t)(r0 + 8) * DIM + col) =
                        __floats2half2_rn(ox1, oy1);
            } else {
                if (r0 < M)
                    *reinterpret_cast<float2*>(outF + (size_t)r0 * DIM + col) =
                        make_float2(ox0, oy0);
                if (r0 + 8 < M)
                    *reinterpret_cast<float2*>(outF + (size_t)(r0 + 8) * DIM + col) =
                        make_float2(ox1, oy1);
            }
        }
    }
}

// ---------------- L2 normalize + ReLU (fp16, ONE matrix) ----------------
__global__ void norm_relu1_kernel(__half* __restrict__ x, int n) {
    int row = blockIdx.x * (blockDim.x >> 5) + (threadIdx.x >> 5);
    if (row >= n) return;
    int lane = threadIdx.x & 31;
    uint4 v = reinterpret_cast<uint4*>(x + (size_t)row * DIM)[lane];
    __half2* h = reinterpret_cast<__half2*>(&v);
    float f[8];
    float s = 0.f;
#pragma unroll
    for (int j = 0; j < 4; j++) {
        float2 p = __half22float2(h[j]);
        f[j * 2] = p.x; f[j * 2 + 1] = p.y;
        s += p.x * p.x + p.y * p.y;
    }
#pragma unroll
    for (int o = 16; o; o >>= 1) s += __shfl_xor_sync(0xFFFFFFFFu, s, o);
    float inv = 1.0f / fmaxf(sqrtf(s), 1e-12f);
    uint4 ov;
    __half2* ho = reinterpret_cast<__half2*>(&ov);
#pragma unroll
    for (int j = 0; j < 4; j++)
        ho[j] = __floats2half2_rn(fmaxf(f[j * 2] * inv, 0.f), fmaxf(f[j * 2 + 1] * inv, 0.f));
    reinterpret_cast<uint4*>(x + (size_t)row * DIM)[lane] = ov;
}

// ---------------- host orchestration ----------------
extern "C" void kernel_launch(void* const* d_in, const int* in_sizes, int n_in,
                              void* d_out, int out_size) {
    (void)in_sizes; (void)n_in; (void)out_size;
    const float* xa_in = (const float*)d_in[0];
    const float* xp_in = (const float*)d_in[1];
    const float* Wl    = (const float*)d_in[2];
    const float* bl    = (const float*)d_in[3];
    const float* Wr    = (const float*)d_in[4];
    const int*   e_ap  = (const int*)d_in[5];
    const int*   e_pa  = (const int*)d_in[6];
    float* out = (float*)d_out;

    __half *xa16, *xp16, *bufA[2], *bufP[2], *aggA, *aggP, *hWl, *hWr;
    int *degA, *degP, *offA, *offP, *curA, *curP, *csrA, *csrP;
    cudaGetSymbolAddress((void**)&xa16, g_xa16);
    cudaGetSymbolAddress((void**)&xp16, g_xp16);
    cudaGetSymbolAddress((void**)&bufA[0], g_bufA0);
    cudaGetSymbolAddress((void**)&bufA[1], g_bufA1);
    cudaGetSymbolAddress((void**)&bufP[0], g_bufP0);
    cudaGetSymbolAddress((void**)&bufP[1], g_bufP1);
    cudaGetSymbolAddress((void**)&aggA, g_aggA);
    cudaGetSymbolAddress((void**)&aggP, g_aggP);
    cudaGetSymbolAddress((void**)&hWl, g_hWl);
    cudaGetSymbolAddress((void**)&hWr, g_hWr);
    cudaGetSymbolAddress((void**)&degA, g_degA);
    cudaGetSymbolAddress((void**)&degP, g_degP);
    cudaGetSymbolAddress((void**)&offA, g_offA);
    cudaGetSymbolAddress((void**)&offP, g_offP);
    cudaGetSymbolAddress((void**)&curA, g_curA);
    cudaGetSymbolAddress((void**)&curP, g_curP);
    cudaGetSymbolAddress((void**)&csrA, g_csrA);
    cudaGetSymbolAddress((void**)&csrP, g_csrP);

    static bool attr_set = false;
    if (!attr_set) {
        cudaFuncSetAttribute(gemm1_kernel, cudaFuncAttributeMaxDynamicSharedMemorySize,
                             6 * STG_H * (int)sizeof(__half));
        attr_set = true;
    }

    cudaStream_t sx = g_aux.s;

    // ---- fork: converts on default stream, CSR build on aux stream ----
    cudaEventRecord(g_aux.fork, 0);
    cudaStreamWaitEvent(sx, g_aux.fork, 0);

    cvt_all_kernel<<<(N_NODES * DIM / 4 + 255) / 256, 256>>>(
        xa_in, xp_in, xa16, xp16, Wl, Wr, hWl, hWr,
        N_NODES * DIM / 4, W_ELEMS / 4);

    cudaMemsetAsync(degA, 0, N_NODES * sizeof(int), sx);
    cudaMemsetAsync(degP, 0, N_NODES * sizeof(int), sx);
    {
        dim3 g((N_EDGES + 255) / 256, 2);
        deg2_kernel<<<g, 256, 0, sx>>>(e_ap + N_EDGES, degP, e_pa + N_EDGES, degA, N_EDGES);
    }
    {
        dim3 g(SNB, 2);
        scan_p1<<<g, 256, 0, sx>>>(degP, degA, N_NODES);
        scan_p2<<<2, 128, 0, sx>>>(offP, offA, N_NODES);
        scan_p3<<<g, 256, 0, sx>>>(degP, degA, offP, curP, offA, curA, N_NODES);
    }
    {
        dim3 g((N_EDGES + 255) / 256, 2);
        fill2_kernel<<<g, 256, 0, sx>>>(e_ap, curP, csrP, e_pa, curA, csrA, N_EDGES);
    }

    cudaEventRecord(g_aux.join, sx);
    cudaStreamWaitEvent(0, g_aux.join, 0);

    const __half* inA = xa16;
    const __half* inP = xp16;

    dim3 gGrid(2, (N_NODES + 127) / 128);    // (2, 391) per direction
    int wBlocks = (N_NODES + 7) / 8;
    const int smemBytes = 6 * STG_H * (int)sizeof(__half);   // 48KB

    for (int l = 0; l < N_LAYERS; l++) {
        const bool last = (l == N_LAYERS - 1);
        __half* outA = last ? nullptr : bufA[l & 1];
        __half* outP = last ? nullptr : bufP[l & 1];
        float* outA_f = last ? out : nullptr;
        float* outP_f = last ? out + (size_t)N_NODES * DIM : nullptr;

        const __half* wl_p = hWl + ((size_t)l * 2 + 0) * DIM * DIM;
        const __half* wr_p = hWr + ((size_t)l * 2 + 0) * DIM * DIM;
        const float*  bl_p = bl + ((size_t)l * 2 + 0) * DIM;
        const __half* wl_a = hWl + ((size_t)l * 2 + 1) * DIM * DIM;
        const __half* wr_a = hWr + ((size_t)l * 2 + 1) * DIM * DIM;
        const float*  bl_a = bl + ((size_t)l * 2 + 1) * DIM;

        // fork the two independent direction chains
        cudaEventRecord(g_aux.fork, 0);
        cudaStreamWaitEvent(sx, g_aux.fork, 0);

        // chain P (default stream)
        gather1_kernel<<<wBlocks, 256>>>(inA, offP, csrP, aggP, N_NODES);
        gemm1_kernel<<<gGrid, 256, smemBytes>>>(aggP, inP, wl_p, wr_p, bl_p,
                                                outP, outP_f, N_NODES);
        if (!last) norm_relu1_kernel<<<wBlocks, 256>>>(outP, N_NODES);

        // chain A (aux stream)
        gather1_kernel<<<wBlocks, 256, 0, sx>>>(inP, offA, csrA, aggA, N_NODES);
        gemm1_kernel<<<gGrid, 256, smemBytes, sx>>>(aggA, inA, wl_a, wr_a, bl_a,
                                                    outA, outA_f, N_NODES);
        if (!last) norm_relu1_kernel<<<wBlocks, 256, 0, sx>>>(outA, N_NODES);

        // join before next layer (cross-direction dependency)
        cudaEventRecord(g_aux.join, sx);
        cudaStreamWaitEvent(0, g_aux.join, 0);

        inA = outA;
        inP = outP;
    }
}

// round 16
// speedup vs baseline: 1.0514x; 1.0059x over previous
#include <cuda_runtime.h>
#include <cuda_fp16.h>
#include <cstdint>
#include <cstddef>

#define N_NODES 50000
#define DIM 256
#define N_EDGES 800000
#define N_LAYERS 5
#define W_ELEMS (N_LAYERS * 2 * DIM * DIM)

#define SCHUNK 512
#define SNB ((N_NODES + SCHUNK - 1) / SCHUNK)   // 98

// ---------------- device scratch (allocation-free: .bss globals) ----------------
__device__ __half g_xa16[N_NODES * DIM];
__device__ __half g_xp16[N_NODES * DIM];
__device__ __half g_bufA0[N_NODES * DIM];
__device__ __half g_bufA1[N_NODES * DIM];
__device__ __half g_bufP0[N_NODES * DIM];
__device__ __half g_bufP1[N_NODES * DIM];
__device__ __half g_aggA[N_NODES * DIM];
__device__ __half g_aggP[N_NODES * DIM];
__device__ __half g_hWl[W_ELEMS];
__device__ __half g_hWr[W_ELEMS];
__device__ int    g_degA[N_NODES];
__device__ int    g_degP[N_NODES];
__device__ int    g_offA[N_NODES + 1];
__device__ int    g_offP[N_NODES + 1];
__device__ int    g_curA[N_NODES];
__device__ int    g_curP[N_NODES];
__device__ int    g_csrA[N_EDGES];
__device__ int    g_csrP[N_EDGES];
__device__ int    g_part[2][SNB];

// ---------------- second stream + events, created once ----------------
struct AuxStream {
    cudaStream_t s;
    cudaEvent_t fork, join;
    AuxStream() {
        cudaStreamCreateWithFlags(&s, cudaStreamNonBlocking);
        cudaEventCreateWithFlags(&fork, cudaEventDisableTiming);
        cudaEventCreateWithFlags(&join, cudaEventDisableTiming);
    }
};
static AuxStream g_aux;

// ---------------- fp32 -> fp16 convert: features + weights in ONE launch ----------------
__global__ void cvt_all_kernel(const float* __restrict__ xa, const float* __restrict__ xp,
                               __half* __restrict__ xah, __half* __restrict__ xph,
                               const float* __restrict__ wl, const float* __restrict__ wr,
                               __half* __restrict__ wlh, __half* __restrict__ wrh,
                               int n4f, int n4w) {
    int i = blockIdx.x * blockDim.x + threadIdx.x;
    if (i < n4f) {
        float4 va = reinterpret_cast<const float4*>(xa)[i];
        float4 vb = reinterpret_cast<const float4*>(xp)[i];
        reinterpret_cast<__half2*>(xah)[i * 2]     = __floats2half2_rn(va.x, va.y);
        reinterpret_cast<__half2*>(xah)[i * 2 + 1] = __floats2half2_rn(va.z, va.w);
        reinterpret_cast<__half2*>(xph)[i * 2]     = __floats2half2_rn(vb.x, vb.y);
        reinterpret_cast<__half2*>(xph)[i * 2 + 1] = __floats2half2_rn(vb.z, vb.w);
    }
    if (i < n4w) {
        float4 va = reinterpret_cast<const float4*>(wl)[i];
        float4 vb = reinterpret_cast<const float4*>(wr)[i];
        reinterpret_cast<__half2*>(wlh)[i * 2]     = __floats2half2_rn(va.x, va.y);
        reinterpret_cast<__half2*>(wlh)[i * 2 + 1] = __floats2half2_rn(va.z, va.w);
        reinterpret_cast<__half2*>(wrh)[i * 2]     = __floats2half2_rn(vb.x, vb.y);
        reinterpret_cast<__half2*>(wrh)[i * 2 + 1] = __floats2half2_rn(vb.z, vb.w);
    }
}

// ---------------- CSR build ----------------
__global__ void deg2_kernel(const int* __restrict__ dstP, int* __restrict__ degP,
                            const int* __restrict__ dstA, int* __restrict__ degA, int E) {
    int e = blockIdx.x * blockDim.x + threadIdx.x;
    if (e < E) {
        if (blockIdx.y == 0) atomicAdd(&degP[dstP[e]], 1);
        else                 atomicAdd(&degA[dstA[e]], 1);
    }
}

__global__ void scan_p1(const int* __restrict__ dP, const int* __restrict__ dA, int n) {
    const int* deg = blockIdx.y ? dA : dP;
    const int tid = threadIdx.x;                 // 256
    int i0 = blockIdx.x * SCHUNK + tid * 2;
    int v = 0;
    if (i0 < n)     v += deg[i0];
    if (i0 + 1 < n) v += deg[i0 + 1];
    __shared__ int ws[8];
#pragma unroll
    for (int o = 16; o; o >>= 1) v += __shfl_xor_sync(0xFFFFFFFFu, v, o);
    if ((tid & 31) == 0) ws[tid >> 5] = v;
    __syncthreads();
    if (tid == 0) {
        int s = 0;
#pragma unroll
        for (int w = 0; w < 8; w++) s += ws[w];
        g_part[blockIdx.y][blockIdx.x] = s;
    }
}

__global__ void scan_p2(int* __restrict__ offP, int* __restrict__ offA, int n) {
    const int dir = blockIdx.x;
    int* off = dir ? offA : offP;
    const int tid = threadIdx.x;                 // 128
    int v = (tid < SNB) ? g_part[dir][tid] : 0;
    __shared__ int ws[4];
    int x = v;
    const int lane = tid & 31, wid = tid >> 5;
#pragma unroll
    for (int o = 1; o < 32; o <<= 1) {
        int y = __shfl_up_sync(0xFFFFFFFFu, x, o);
        if (lane >= o) x += y;
    }
    if (lane == 31) ws[wid] = x;
    __syncthreads();
    if (tid < 4) {
        int w = ws[tid];
#pragma unroll
        for (int o = 1; o < 4; o <<= 1) {
            int y = __shfl_up_sync(0xFu, w, o);
            if (tid >= o) w += y;
        }
        ws[tid] = w;
    }
    __syncthreads();
    int incl = x + (wid ? ws[wid - 1] : 0);
    if (tid < SNB) g_part[dir][tid] = incl - v;
    if (tid == 127) off[n] = incl;
}

__global__ void scan_p3(const int* __restrict__ dP, const int* __restrict__ dA,
                        int* __restrict__ offP, int* __restrict__ curP,
                        int* __restrict__ offA, int* __restrict__ curA, int n) {
    const int dir = blockIdx.y;
    const int* deg = dir ? dA : dP;
    int* off = dir ? offA : offP;
    int* cur = dir ? curA : curP;
    const int tid = threadIdx.x;                 // 256
    const int base = g_part[dir][blockIdx.x];
    int i0 = blockIdx.x * SCHUNK + tid * 2;
    int v0 = (i0 < n) ? deg[i0] : 0;
    int v1 = (i0 + 1 < n) ? deg[i0 + 1] : 0;
    int sum = v0 + v1;

    __shared__ int ws[8];
    int x = sum;
    const int lane = tid & 31, wid = tid >> 5;
#pragma unroll
    for (int o = 1; o < 32; o <<= 1) {
        int y = __shfl_up_sync(0xFFFFFFFFu, x, o);
        if (lane >= o) x += y;
    }
    if (lane == 31) ws[wid] = x;
    __syncthreads();
    if (tid < 8) {
        int w = ws[tid];
#pragma unroll
        for (int o = 1; o < 8; o <<= 1) {
            int y = __shfl_up_sync(0xFFu, w, o);
            if (tid >= o) w += y;
        }
        ws[tid] = w;
    }
    __syncthreads();
    int excl = x - sum + (wid ? ws[wid - 1] : 0);
    int p = base + excl;
    if (i0 < n)     { off[i0] = p;          cur[i0] = p; }
    if (i0 + 1 < n) { off[i0 + 1] = p + v0; cur[i0 + 1] = p + v0; }
}

__global__ void fill2_kernel(const int* __restrict__ eap, int* __restrict__ curP, int* __restrict__ csrP,
                             const int* __restrict__ epa, int* __restrict__ curA, int* __restrict__ csrA,
                             int E) {
    int e = blockIdx.x * blockDim.x + threadIdx.x;
    if (e < E) {
        if (blockIdx.y == 0) {
            int slot = atomicAdd(&curP[eap[E + e]], 1);
            csrP[slot] = eap[e];
        } else {
            int slot = atomicAdd(&curA[epa[E + e]], 1);
            csrA[slot] = epa[e];
        }
    }
}

// ---------------- gather (fp16 rows; ONE direction; shuffle-preloaded indices) ------
// Warp preloads its full neighbor list (deg<=32 common case) in ONE coalesced load;
// loop indices come from __shfl_sync — no memory op in the dependency chain.
__global__ void gather1_kernel(const __half* __restrict__ x, const int* __restrict__ off,
                               const int* __restrict__ csr, __half* __restrict__ agg, int n) {
    int row = blockIdx.x * (blockDim.x >> 5) + (threadIdx.x >> 5);
    if (row >= n) return;
    const int lane = threadIdx.x & 31;
    const int beg = off[row], end = off[row + 1];
    const int deg = end - beg;

    // coalesced preload of the neighbor list (first 32 entries)
    int myIdx = (beg + lane < end) ? csr[beg + lane] : 0;
    const int dmin = deg < 32 ? deg : 32;

    float s[8] = {0.f, 0.f, 0.f, 0.f, 0.f, 0.f, 0.f, 0.f};
    int e = 0;
    for (; e + 1 < dmin; e += 2) {
        int i0 = __shfl_sync(0xFFFFFFFFu, myIdx, e);
        int i1 = __shfl_sync(0xFFFFFFFFu, myIdx, e + 1);
        uint4 v0 = reinterpret_cast<const uint4*>(x + (size_t)i0 * DIM)[lane];
        uint4 v1 = reinterpret_cast<const uint4*>(x + (size_t)i1 * DIM)[lane];
        const __half2* h0 = reinterpret_cast<const __half2*>(&v0);
        const __half2* h1 = reinterpret_cast<const __half2*>(&v1);
#pragma unroll
        for (int j = 0; j < 4; j++) {
            float2 f0 = __half22float2(h0[j]);
            float2 f1 = __half22float2(h1[j]);
            s[j * 2]     += f0.x + f1.x;
            s[j * 2 + 1] += f0.y + f1.y;
        }
    }
    if (e < dmin) {
        int i0 = __shfl_sync(0xFFFFFFFFu, myIdx, e);
        uint4 v0 = reinterpret_cast<const uint4*>(x + (size_t)i0 * DIM)[lane];
        const __half2* h0 = reinterpret_cast<const __half2*>(&v0);
#pragma unroll
        for (int j = 0; j < 4; j++) {
            float2 f0 = __half22float2(h0[j]);
            s[j * 2]     += f0.x;
            s[j * 2 + 1] += f0.y;
        }
    }
    // rare tail: degree > 32 (P ~ 2e-4 per row) — direct loads, any degree correct
    for (int t = 32; t < deg; t++) {
        uint4 v0 = reinterpret_cast<const uint4*>(x + (size_t)csr[beg + t] * DIM)[lane];
        const __half2* h0 = reinterpret_cast<const __half2*>(&v0);
#pragma unroll
        for (int j = 0; j < 4; j++) {
            float2 f0 = __half22float2(h0[j]);
            s[j * 2]     += f0.x;
            s[j * 2 + 1] += f0.y;
        }
    }

    const float inv = 1.0f / fmaxf((float)deg, 1.0f);
    uint4 o;
    __half2* ho = reinterpret_cast<__half2*>(&o);
#pragma unroll
    for (int j = 0; j < 4; j++)
        ho[j] = __floats2half2_rn(s[j * 2] * inv, s[j * 2 + 1] * inv);
    reinterpret_cast<uint4*>(agg + (size_t)row * DIM)[lane] = o;
}

// ---------------- fp16 tensor-core fused dual-input GEMM (ONE direction) ----------------
// out = agg @ Wl^T + self @ Wr^T + b (fp32 accum). m16n8k16, BM=128, BN=128, BK=32,
// 3-stage cp.async, XOR-swizzled smem, LDSM.x4 fragments, 8 warps, warp tile 32x64.

__device__ __forceinline__ void cp_async16(void* smem, const void* gmem, bool pred) {
    uint32_t s = (uint32_t)__cvta_generic_to_shared(smem);
    int sz = pred ? 16 : 0;
    asm volatile("cp.async.cg.shared.global [%0], [%1], 16, %2;"
                 :: "r"(s), "l"(gmem), "r"(sz));
}

#define LDSM_X4(r0, r1, r2, r3, addr)                                     \
    asm volatile("ldmatrix.sync.aligned.m8n8.x4.shared.b16 "              \
                 "{%0,%1,%2,%3}, [%4];"                                   \
                 : "=r"(r0), "=r"(r1), "=r"(r2), "=r"(r3) : "r"(addr))

#define STG_H (128 * 32)   // halfs per tile per stage (8KB)

__global__ __launch_bounds__(256, 2)
void gemm1_kernel(const __half* __restrict__ Aagg, const __half* __restrict__ Aself,
                  const __half* __restrict__ Wl, const __half* __restrict__ Wr,
                  const float* __restrict__ bias,
                  __half* __restrict__ outH, float* __restrict__ outF, int M) {
    extern __shared__ __half sm[];
    __half* As = sm;                 // [3][128][32] XOR-swizzled
    __half* Bs = sm + 3 * STG_H;

    const int bm = blockIdx.y * 128;
    const int bn = blockIdx.x * 128;
    const int t = threadIdx.x;
    const int wid = t >> 5;
    const int lane = t & 31;
    const int wm = wid & 3;
    const int wn = wid >> 2;
    const int gid = lane >> 2;
    const int tig = lane & 3;

    const uint32_t smem_u32 = (uint32_t)__cvta_generic_to_shared(sm);
    const uint32_t baseA = smem_u32;
    const uint32_t baseB = smem_u32 + 3 * STG_H * 2;

    const int matq = lane >> 3;
    const int rq = lane & 7;
    const int kselA = matq >> 1;
    uint32_t rowA[2]; int swA[2];
#pragma unroll
    for (int mi = 0; mi < 2; mi++) {
        int row = wm * 32 + mi * 16 + (matq & 1) * 8 + rq;
        rowA[mi] = row * 64;
        swA[mi] = (row >> 1) & 3;
    }
    const int kselB = matq & 1;
    uint32_t rowB[4]; int swB[4];
#pragma unroll
    for (int j = 0; j < 4; j++) {
        int ni = 2 * j + (matq >> 1);
        int row = wn * 64 + ni * 8 + rq;
        rowB[j] = row * 64;
        swB[j] = (row >> 1) & 3;
    }

    float acc[2][8][4];
#pragma unroll
    for (int mi = 0; mi < 2; mi++)
#pragma unroll
        for (int ni = 0; ni < 8; ni++)
#pragma unroll
            for (int j = 0; j < 4; j++) acc[mi][ni][j] = 0.0f;

    auto load_tile = [&](int stage, int kt) {
        const int phase = kt >> 3;
        const int kloc = (kt & 7) << 5;
        const __half* Ap = phase ? Aself : Aagg;
        const __half* Bp = phase ? Wr : Wl;
        __half* as = As + stage * STG_H;
        __half* bs = Bs + stage * STG_H;
#pragma unroll
        for (int i = 0; i < 2; i++) {
            int c = t + i * 256;
            int row = c >> 2;
            int seg = c & 3;
            int segp = seg ^ ((row >> 1) & 3);
            int gr = bm + row;
            cp_async16(as + row * 32 + segp * 8,
                       Ap + (size_t)gr * DIM + kloc + seg * 8, gr < M);
            cp_async16(bs + row * 32 + segp * 8,
                       Bp + (size_t)(bn + row) * DIM + kloc + seg * 8, true);
        }
        asm volatile("cp.async.commit_group;" ::: "memory");
    };

    load_tile(0, 0);
    load_tile(1, 1);

#pragma unroll 1
    for (int kt = 0; kt < 16; kt++) {
        const int s = kt % 3;
        if (kt < 15)
            asm volatile("cp.async.wait_group 1;" ::: "memory");
        else
            asm volatile("cp.async.wait_group 0;" ::: "memory");   // final tile must be fully resident
        __syncthreads();
        if (kt + 2 < 16) load_tile((kt + 2) % 3, kt + 2);

        const uint32_t sA = baseA + s * (STG_H * 2);
        const uint32_t sB = baseB + s * (STG_H * 2);

#pragma unroll
        for (int ks = 0; ks < 2; ks++) {
            const int gA = ks * 2;
            uint32_t aR[2][4];
#pragma unroll
            for (int mi = 0; mi < 2; mi++) {
                uint32_t addr = sA + rowA[mi] + (uint32_t)(((gA + kselA) ^ swA[mi]) << 4);
                LDSM_X4(aR[mi][0], aR[mi][1], aR[mi][2], aR[mi][3], addr);
            }
            uint32_t bR[8][2];
#pragma unroll
            for (int j = 0; j < 4; j++) {
                uint32_t addr = sB + rowB[j] + (uint32_t)(((gA + kselB) ^ swB[j]) << 4);
                LDSM_X4(bR[2 * j][0], bR[2 * j][1], bR[2 * j + 1][0], bR[2 * j + 1][1], addr);
            }
#pragma unroll
            for (int mi = 0; mi < 2; mi++)
#pragma unroll
                for (int ni = 0; ni < 8; ni++) {
                    asm volatile(
                        "mma.sync.aligned.m16n8k16.row.col.f32.f16.f16.f32 "
                        "{%0,%1,%2,%3}, {%4,%5,%6,%7}, {%8,%9}, {%0,%1,%2,%3};"
                        : "+f"(acc[mi][ni][0]), "+f"(acc[mi][ni][1]),
                          "+f"(acc[mi][ni][2]), "+f"(acc[mi][ni][3])
                        : "r"(aR[mi][0]), "r"(aR[mi][1]), "r"(aR[mi][2]), "r"(aR[mi][3]),
                          "r"(bR[ni][0]), "r"(bR[ni][1]));
                }
        }
    }

#pragma unroll
    for (int ni = 0; ni < 8; ni++) {
        int col = bn + wn * 64 + ni * 8 + 2 * tig;
        float bx = bias[col], by = bias[col + 1];
#pragma unroll
        for (int mi = 0; mi < 2; mi++) {
            int r0 = bm + wm * 32 + mi * 16 + gid;
            float ox0 = acc[mi][ni][0] + bx, oy0 = acc[mi][ni][1] + by;
            float ox1 = acc[mi][ni][2] + bx, oy1 = acc[mi][ni][3] + by;
            if (outH) {
                if (r0 < M)
                    *reinterpret_cast<__half2*>(outH + (size_t)r0 * DIM + col) =
                        __floats2half2_rn(ox0, oy0);
                if (r0 + 8 < M)
                    *reinterpret_cast<__half2*>(outH + (size_t)(r0 + 8) * DIM + col) =
                        __floats2half2_rn(ox1, oy1);
            } else {
                if (r0 < M)
                    *reinterpret_cast<float2*>(outF + (size_t)r0 * DIM + col) =
                        make_float2(ox0, oy0);
                if (r0 + 8 < M)
                    *reinterpret_cast<float2*>(outF + (size_t)(r0 + 8) * DIM + col) =
                        make_float2(ox1, oy1);
            }
        }
    }
}

// ---------------- L2 normalize + ReLU (fp16, ONE matrix) ----------------
__global__ void norm_relu1_kernel(__half* __restrict__ x, int n) {
    int row = blockIdx.x * (blockDim.x >> 5) + (threadIdx.x >> 5);
    if (row >= n) return;
    int lane = threadIdx.x & 31;
    uint4 v = reinterpret_cast<uint4*>(x + (size_t)row * DIM)[lane];
    __half2* h = reinterpret_cast<__half2*>(&v);
    float f[8];
    float s = 0.f;
#pragma unroll
    for (int j = 0; j < 4; j++) {
        float2 p = __half22float2(h[j]);
        f[j * 2] = p.x; f[j * 2 + 1] = p.y;
        s += p.x * p.x + p.y * p.y;
    }
#pragma unroll
    for (int o = 16; o; o >>= 1) s += __shfl_xor_sync(0xFFFFFFFFu, s, o);
    float inv = 1.0f / fmaxf(sqrtf(s), 1e-12f);
    uint4 ov;
    __half2* ho = reinterpret_cast<__half2*>(&ov);
#pragma unroll
    for (int j = 0; j < 4; j++)
        ho[j] = __floats2half2_rn(fmaxf(f[j * 2] * inv, 0.f), fmaxf(f[j * 2 + 1] * inv, 0.f));
    reinterpret_cast<uint4*>(x + (size_t)row * DIM)[lane] = ov;
}

// ---------------- host orchestration ----------------
extern "C" void kernel_launch(void* const* d_in, const int* in_sizes, int n_in,
                              void* d_out, int out_size) {
    (void)in_sizes; (void)n_in; (void)out_size;
    const float* xa_in = (const float*)d_in[0];
    const float* xp_in = (const float*)d_in[1];
    const float* Wl    = (const float*)d_in[2];
    const float* bl    = (const float*)d_in[3];
    const float* Wr    = (const float*)d_in[4];
    const int*   e_ap  = (const int*)d_in[5];
    const int*   e_pa  = (const int*)d_in[6];
    float* out = (float*)d_out;

    __half *xa16, *xp16, *bufA[2], *bufP[2], *aggA, *aggP, *hWl, *hWr;
    int *degA, *degP, *offA, *offP, *curA, *curP, *csrA, *csrP;
    cudaGetSymbolAddress((void**)&xa16, g_xa16);
    cudaGetSymbolAddress((void**)&xp16, g_xp16);
    cudaGetSymbolAddress((void**)&bufA[0], g_bufA0);
    cudaGetSymbolAddress((void**)&bufA[1], g_bufA1);
    cudaGetSymbolAddress((void**)&bufP[0], g_bufP0);
    cudaGetSymbolAddress((void**)&bufP[1], g_bufP1);
    cudaGetSymbolAddress((void**)&aggA, g_aggA);
    cudaGetSymbolAddress((void**)&aggP, g_aggP);
    cudaGetSymbolAddress((void**)&hWl, g_hWl);
    cudaGetSymbolAddress((void**)&hWr, g_hWr);
    cudaGetSymbolAddress((void**)&degA, g_degA);
    cudaGetSymbolAddress((void**)&degP, g_degP);
    cudaGetSymbolAddress((void**)&offA, g_offA);
    cudaGetSymbolAddress((void**)&offP, g_offP);
    cudaGetSymbolAddress((void**)&curA, g_curA);
    cudaGetSymbolAddress((void**)&curP, g_curP);
    cudaGetSymbolAddress((void**)&csrA, g_csrA);
    cudaGetSymbolAddress((void**)&csrP, g_csrP);

    static bool attr_set = false;
    if (!attr_set) {
        cudaFuncSetAttribute(gemm1_kernel, cudaFuncAttributeMaxDynamicSharedMemorySize,
                             6 * STG_H * (int)sizeof(__half));
        attr_set = true;
    }

    cudaStream_t sx = g_aux.s;

    // ---- fork: converts on default stream, CSR build on aux stream ----
    cudaEventRecord(g_aux.fork, 0);
    cudaStreamWaitEvent(sx, g_aux.fork, 0);

    cvt_all_kernel<<<(N_NODES * DIM / 4 + 255) / 256, 256>>>(
        xa_in, xp_in, xa16, xp16, Wl, Wr, hWl, hWr,
        N_NODES * DIM / 4, W_ELEMS / 4);

    cudaMemsetAsync(degA, 0, N_NODES * sizeof(int), sx);
    cudaMemsetAsync(degP, 0, N_NODES * sizeof(int), sx);
    {
        dim3 g((N_EDGES + 255) / 256, 2);
        deg2_kernel<<<g, 256, 0, sx>>>(e_ap + N_EDGES, degP, e_pa + N_EDGES, degA, N_EDGES);
    }
    {
        dim3 g(SNB, 2);
        scan_p1<<<g, 256, 0, sx>>>(degP, degA, N_NODES);
        scan_p2<<<2, 128, 0, sx>>>(offP, offA, N_NODES);
        scan_p3<<<g, 256, 0, sx>>>(degP, degA, offP, curP, offA, curA, N_NODES);
    }
    {
        dim3 g((N_EDGES + 255) / 256, 2);
        fill2_kernel<<<g, 256, 0, sx>>>(e_ap, curP, csrP, e_pa, curA, csrA, N_EDGES);
    }

    cudaEventRecord(g_aux.join, sx);
    cudaStreamWaitEvent(0, g_aux.join, 0);

    const __half* inA = xa16;
    const __half* inP = xp16;

    dim3 gGrid(2, (N_NODES + 127) / 128);    // (2, 391) per direction
    int wBlocks = (N_NODES + 7) / 8;
    const int smemBytes = 6 * STG_H * (int)sizeof(__half);   // 48KB

    for (int l = 0; l < N_LAYERS; l++) {
        const bool last = (l == N_LAYERS - 1);
        __half* outA = last ? nullptr : bufA[l & 1];
        __half* outP = last ? nullptr : bufP[l & 1];
        float* outA_f = last ? out : nullptr;
        float* outP_f = last ? out + (size_t)N_NODES * DIM : nullptr;

        const __half* wl_p = hWl + ((size_t)l * 2 + 0) * DIM * DIM;
        const __half* wr_p = hWr + ((size_t)l * 2 + 0) * DIM * DIM;
        const float*  bl_p = bl + ((size_t)l * 2 + 0) * DIM;
        const __half* wl_a = hWl + ((size_t)l * 2 + 1) * DIM * DIM;
        const __half* wr_a = hWr + ((size_t)l * 2 + 1) * DIM * DIM;
        const float*  bl_a = bl + ((size_t)l * 2 + 1) * DIM;

        // fork the two independent direction chains
        cudaEventRecord(g_aux.fork, 0);
        cudaStreamWaitEvent(sx, g_aux.fork, 0);

        // chain P (default stream)
        gather1_kernel<<<wBlocks, 256>>>(inA, offP, csrP, aggP, N_NODES);
        gemm1_kernel<<<gGrid, 256, smemBytes>>>(aggP, inP, wl_p, wr_p, bl_p,
                                                outP, outP_f, N_NODES);
        if (!last) norm_relu1_kernel<<<wBlocks, 256>>>(outP, N_NODES);

        // chain A (aux stream)
        gather1_kernel<<<wBlocks, 256, 0, sx>>>(inP, offA, csrA, aggA, N_NODES);
        gemm1_kernel<<<gGrid, 256, smemBytes, sx>>>(aggA, inA, wl_a, wr_a, bl_a,
                                                    outA, outA_f, N_NODES);
        if (!last) norm_relu1_kernel<<<wBlocks, 256, 0, sx>>>(outA, N_NODES);

        // join before next layer (cross-direction dependency)
        cudaEventRecord(g_aux.join, sx);
        cudaStreamWaitEvent(0, g_aux.join, 0);

        inA = outA;
        inP = outP;
    }
}

// round 17
// speedup vs baseline: 1.0540x; 1.0025x over previous
#include <cuda_runtime.h>
#include <cuda_fp16.h>
#include <cstdint>
#include <cstddef>

#define N_NODES 50000
#define DIM 256
#define N_EDGES 800000
#define N_LAYERS 5
#define W_ELEMS (N_LAYERS * 2 * DIM * DIM)

#define SCHUNK 512
#define SNB ((N_NODES + SCHUNK - 1) / SCHUNK)   // 98

// ---------------- device scratch (allocation-free: .bss globals) ----------------
__device__ __half g_xa16[N_NODES * DIM];
__device__ __half g_xp16[N_NODES * DIM];
__device__ __half g_bufA0[N_NODES * DIM];
__device__ __half g_bufA1[N_NODES * DIM];
__device__ __half g_bufP0[N_NODES * DIM];
__device__ __half g_bufP1[N_NODES * DIM];
__device__ __half g_aggA[N_NODES * DIM];
__device__ __half g_aggP[N_NODES * DIM];
__device__ __half g_hWl[W_ELEMS];
__device__ __half g_hWr[W_ELEMS];
__device__ int    g_degA[N_NODES];
__device__ int    g_degP[N_NODES];
__device__ int    g_offA[N_NODES + 1];
__device__ int    g_offP[N_NODES + 1];
__device__ int    g_curA[N_NODES];
__device__ int    g_curP[N_NODES];
__device__ int    g_csrA[N_EDGES];
__device__ int    g_csrP[N_EDGES];
__device__ int    g_part[2][SNB];

// ---------------- second stream + events, created once ----------------
struct AuxStream {
    cudaStream_t s;
    cudaEvent_t fork, join;
    AuxStream() {
        cudaStreamCreateWithFlags(&s, cudaStreamNonBlocking);
        cudaEventCreateWithFlags(&fork, cudaEventDisableTiming);
        cudaEventCreateWithFlags(&join, cudaEventDisableTiming);
    }
};
static AuxStream g_aux;

// ---------------- fp32 -> fp16 convert: features + weights in ONE launch ----------------
__global__ void cvt_all_kernel(const float* __restrict__ xa, const float* __restrict__ xp,
                               __half* __restrict__ xah, __half* __restrict__ xph,
                               const float* __restrict__ wl, const float* __restrict__ wr,
                               __half* __restrict__ wlh, __half* __restrict__ wrh,
                               int n4f, int n4w) {
    int i = blockIdx.x * blockDim.x + threadIdx.x;
    if (i < n4f) {
        float4 va = reinterpret_cast<const float4*>(xa)[i];
        float4 vb = reinterpret_cast<const float4*>(xp)[i];
        reinterpret_cast<__half2*>(xah)[i * 2]     = __floats2half2_rn(va.x, va.y);
        reinterpret_cast<__half2*>(xah)[i * 2 + 1] = __floats2half2_rn(va.z, va.w);
        reinterpret_cast<__half2*>(xph)[i * 2]     = __floats2half2_rn(vb.x, vb.y);
        reinterpret_cast<__half2*>(xph)[i * 2 + 1] = __floats2half2_rn(vb.z, vb.w);
    }
    if (i < n4w) {
        float4 va = reinterpret_cast<const float4*>(wl)[i];
        float4 vb = reinterpret_cast<const float4*>(wr)[i];
        reinterpret_cast<__half2*>(wlh)[i * 2]     = __floats2half2_rn(va.x, va.y);
        reinterpret_cast<__half2*>(wlh)[i * 2 + 1] = __floats2half2_rn(va.z, va.w);
        reinterpret_cast<__half2*>(wrh)[i * 2]     = __floats2half2_rn(vb.x, vb.y);
        reinterpret_cast<__half2*>(wrh)[i * 2 + 1] = __floats2half2_rn(vb.z, vb.w);
    }
}

// ---------------- CSR build ----------------
__global__ void deg2_kernel(const int* __restrict__ dstP, int* __restrict__ degP,
                            const int* __restrict__ dstA, int* __restrict__ degA, int E) {
    int e = blockIdx.x * blockDim.x + threadIdx.x;
    if (e < E) {
        if (blockIdx.y == 0) atomicAdd(&degP[dstP[e]], 1);
        else                 atomicAdd(&degA[dstA[e]], 1);
    }
}

__global__ void scan_p1(const int* __restrict__ dP, const int* __restrict__ dA, int n) {
    const int* deg = blockIdx.y ? dA : dP;
    const int tid = threadIdx.x;                 // 256
    int i0 = blockIdx.x * SCHUNK + tid * 2;
    int v = 0;
    if (i0 < n)     v += deg[i0];
    if (i0 + 1 < n) v += deg[i0 + 1];
    __shared__ int ws[8];
#pragma unroll
    for (int o = 16; o; o >>= 1) v += __shfl_xor_sync(0xFFFFFFFFu, v, o);
    if ((tid & 31) == 0) ws[tid >> 5] = v;
    __syncthreads();
    if (tid == 0) {
        int s = 0;
#pragma unroll
        for (int w = 0; w < 8; w++) s += ws[w];
        g_part[blockIdx.y][blockIdx.x] = s;
    }
}

__global__ void scan_p2(int* __restrict__ offP, int* __restrict__ offA, int n) {
    const int dir = blockIdx.x;
    int* off = dir ? offA : offP;
    const int tid = threadIdx.x;                 // 128
    int v = (tid < SNB) ? g_part[dir][tid] : 0;
    __shared__ int ws[4];
    int x = v;
    const int lane = tid & 31, wid = tid >> 5;
#pragma unroll
    for (int o = 1; o < 32; o <<= 1) {
        int y = __shfl_up_sync(0xFFFFFFFFu, x, o);
        if (lane >= o) x += y;
    }
    if (lane == 31) ws[wid] = x;
    __syncthreads();
    if (tid < 4) {
        int w = ws[tid];
#pragma unroll
        for (int o = 1; o < 4; o <<= 1) {
            int y = __shfl_up_sync(0xFu, w, o);
            if (tid >= o) w += y;
        }
        ws[tid] = w;
    }
    __syncthreads();
    int incl = x + (wid ? ws[wid - 1] : 0);
    if (tid < SNB) g_part[dir][tid] = incl - v;
    if (tid == 127) off[n] = incl;
}

__global__ void scan_p3(const int* __restrict__ dP, const int* __restrict__ dA,
                        int* __restrict__ offP, int* __restrict__ curP,
                        int* __restrict__ offA, int* __restrict__ curA, int n) {
    const int dir = blockIdx.y;
    const int* deg = dir ? dA : dP;
    int* off = dir ? offA : offP;
    int* cur = dir ? curA : curP;
    const int tid = threadIdx.x;                 // 256
    const int base = g_part[dir][blockIdx.x];
    int i0 = blockIdx.x * SCHUNK + tid * 2;
    int v0 = (i0 < n) ? deg[i0] : 0;
    int v1 = (i0 + 1 < n) ? deg[i0 + 1] : 0;
    int sum = v0 + v1;

    __shared__ int ws[8];
    int x = sum;
    const int lane = tid & 31, wid = tid >> 5;
#pragma unroll
    for (int o = 1; o < 32; o <<= 1) {
        int y = __shfl_up_sync(0xFFFFFFFFu, x, o);
        if (lane >= o) x += y;
    }
    if (lane == 31) ws[wid] = x;
    __syncthreads();
    if (tid < 8) {
        int w = ws[tid];
#pragma unroll
        for (int o = 1; o < 8; o <<= 1) {
            int y = __shfl_up_sync(0xFFu, w, o);
            if (tid >= o) w += y;
        }
        ws[tid] = w;
    }
    __syncthreads();
    int excl = x - sum + (wid ? ws[wid - 1] : 0);
    int p = base + excl;
    if (i0 < n)     { off[i0] = p;          cur[i0] = p; }
    if (i0 + 1 < n) { off[i0 + 1] = p + v0; cur[i0 + 1] = p + v0; }
}

__global__ void fill2_kernel(const int* __restrict__ eap, int* __restrict__ curP, int* __restrict__ csrP,
                             const int* __restrict__ epa, int* __restrict__ curA, int* __restrict__ csrA,
                             int E) {
    int e = blockIdx.x * blockDim.x + threadIdx.x;
    if (e < E) {
        if (blockIdx.y == 0) {
            int slot = atomicAdd(&curP[eap[E + e]], 1);
            csrP[slot] = eap[e];
        } else {
            int slot = atomicAdd(&curA[epa[E + e]], 1);
            csrA[slot] = epa[e];
        }
    }
}

// ---------------- gather (fp16 rows; ONE direction; shuffle-preloaded indices) ------
__global__ void gather1_kernel(const __half* __restrict__ x, const int* __restrict__ off,
                               const int* __restrict__ csr, __half* __restrict__ agg, int n) {
    int row = blockIdx.x * (blockDim.x >> 5) + (threadIdx.x >> 5);
    if (row >= n) return;
    const int lane = threadIdx.x & 31;
    const int beg = off[row], end = off[row + 1];
    const int deg = end - beg;

    int myIdx = (beg + lane < end) ? csr[beg + lane] : 0;
    const int dmin = deg < 32 ? deg : 32;

    float s[8] = {0.f, 0.f, 0.f, 0.f, 0.f, 0.f, 0.f, 0.f};
    int e = 0;
    for (; e + 1 < dmin; e += 2) {
        int i0 = __shfl_sync(0xFFFFFFFFu, myIdx, e);
        int i1 = __shfl_sync(0xFFFFFFFFu, myIdx, e + 1);
        uint4 v0 = reinterpret_cast<const uint4*>(x + (size_t)i0 * DIM)[lane];
        uint4 v1 = reinterpret_cast<const uint4*>(x + (size_t)i1 * DIM)[lane];
        const __half2* h0 = reinterpret_cast<const __half2*>(&v0);
        const __half2* h1 = reinterpret_cast<const __half2*>(&v1);
#pragma unroll
        for (int j = 0; j < 4; j++) {
            float2 f0 = __half22float2(h0[j]);
            float2 f1 = __half22float2(h1[j]);
            s[j * 2]     += f0.x + f1.x;
            s[j * 2 + 1] += f0.y + f1.y;
        }
    }
    if (e < dmin) {
        int i0 = __shfl_sync(0xFFFFFFFFu, myIdx, e);
        uint4 v0 = reinterpret_cast<const uint4*>(x + (size_t)i0 * DIM)[lane];
        const __half2* h0 = reinterpret_cast<const __half2*>(&v0);
#pragma unroll
        for (int j = 0; j < 4; j++) {
            float2 f0 = __half22float2(h0[j]);
            s[j * 2]     += f0.x;
            s[j * 2 + 1] += f0.y;
        }
    }
    for (int t = 32; t < deg; t++) {   // rare deg>32 tail, correct for any degree
        uint4 v0 = reinterpret_cast<const uint4*>(x + (size_t)csr[beg + t] * DIM)[lane];
        const __half2* h0 = reinterpret_cast<const __half2*>(&v0);
#pragma unroll
        for (int j = 0; j < 4; j++) {
            float2 f0 = __half22float2(h0[j]);
            s[j * 2]     += f0.x;
            s[j * 2 + 1] += f0.y;
        }
    }

    const float inv = 1.0f / fmaxf((float)deg, 1.0f);
    uint4 o;
    __half2* ho = reinterpret_cast<__half2*>(&o);
#pragma unroll
    for (int j = 0; j < 4; j++)
        ho[j] = __floats2half2_rn(s[j * 2] * inv, s[j * 2 + 1] * inv);
    reinterpret_cast<uint4*>(agg + (size_t)row * DIM)[lane] = o;
}

// ---------------- fp16 tensor-core fused dual-input GEMM (ONE direction) ----------------
__device__ __forceinline__ void cp_async16(void* smem, const void* gmem, bool pred) {
    uint32_t s = (uint32_t)__cvta_generic_to_shared(smem);
    int sz = pred ? 16 : 0;
    asm volatile("cp.async.cg.shared.global [%0], [%1], 16, %2;"
                 :: "r"(s), "l"(gmem), "r"(sz));
}

#define LDSM_X4(r0, r1, r2, r3, addr)                                     \
    asm volatile("ldmatrix.sync.aligned.m8n8.x4.shared.b16 "              \
                 "{%0,%1,%2,%3}, [%4];"                                   \
                 : "=r"(r0), "=r"(r1), "=r"(r2), "=r"(r3) : "r"(addr))

#define STG_H (128 * 32)   // halfs per tile per stage (8KB)

__global__ __launch_bounds__(256, 2)
void gemm1_kernel(const __half* __restrict__ Aagg, const __half* __restrict__ Aself,
                  const __half* __restrict__ Wl, const __half* __restrict__ Wr,
                  const float* __restrict__ bias,
                  __half* __restrict__ outH, float* __restrict__ outF, int M) {
    extern __shared__ __half sm[];
    __half* As = sm;                 // [3][128][32] XOR-swizzled
    __half* Bs = sm + 3 * STG_H;

    const int bm = blockIdx.y * 128;
    const int bn = blockIdx.x * 128;
    const int t = threadIdx.x;
    const int wid = t >> 5;
    const int lane = t & 31;
    const int wm = wid & 3;
    const int wn = wid >> 2;
    const int gid = lane >> 2;
    const int tig = lane & 3;

    const uint32_t smem_u32 = (uint32_t)__cvta_generic_to_shared(sm);
    const uint32_t baseA = smem_u32;
    const uint32_t baseB = smem_u32 + 3 * STG_H * 2;

    const int matq = lane >> 3;
    const int rq = lane & 7;
    const int kselA = matq >> 1;
    uint32_t rowA[2]; int swA[2];
#pragma unroll
    for (int mi = 0; mi < 2; mi++) {
        int row = wm * 32 + mi * 16 + (matq & 1) * 8 + rq;
        rowA[mi] = row * 64;
        swA[mi] = (row >> 1) & 3;
    }
    const int kselB = matq & 1;
    uint32_t rowB[4]; int swB[4];
#pragma unroll
    for (int j = 0; j < 4; j++) {
        int ni = 2 * j + (matq >> 1);
        int row = wn * 64 + ni * 8 + rq;
        rowB[j] = row * 64;
        swB[j] = (row >> 1) & 3;
    }

    float acc[2][8][4];
#pragma unroll
    for (int mi = 0; mi < 2; mi++)
#pragma unroll
        for (int ni = 0; ni < 8; ni++)
#pragma unroll
            for (int j = 0; j < 4; j++) acc[mi][ni][j] = 0.0f;

    auto load_tile = [&](int stage, int kt) {
        const int phase = kt >> 3;
        const int kloc = (kt & 7) << 5;
        const __half* Ap = phase ? Aself : Aagg;
        const __half* Bp = phase ? Wr : Wl;
        __half* as = As + stage * STG_H;
        __half* bs = Bs + stage * STG_H;
#pragma unroll
        for (int i = 0; i < 2; i++) {
            int c = t + i * 256;
            int row = c >> 2;
            int seg = c & 3;
            int segp = seg ^ ((row >> 1) & 3);
            int gr = bm + row;
            cp_async16(as + row * 32 + segp * 8,
                       Ap + (size_t)gr * DIM + kloc + seg * 8, gr < M);
            cp_async16(bs + row * 32 + segp * 8,
                       Bp + (size_t)(bn + row) * DIM + kloc + seg * 8, true);
        }
        asm volatile("cp.async.commit_group;" ::: "memory");
    };

    load_tile(0, 0);
    load_tile(1, 1);

#pragma unroll 1
    for (int kt = 0; kt < 16; kt++) {
        const int s = kt % 3;
        if (kt < 15)
            asm volatile("cp.async.wait_group 1;" ::: "memory");
        else
            asm volatile("cp.async.wait_group 0;" ::: "memory");
        __syncthreads();
        if (kt + 2 < 16) load_tile((kt + 2) % 3, kt + 2);

        const uint32_t sA = baseA + s * (STG_H * 2);
        const uint32_t sB = baseB + s * (STG_H * 2);

#pragma unroll
        for (int ks = 0; ks < 2; ks++) {
            const int gA = ks * 2;
            uint32_t aR[2][4];
#pragma unroll
            for (int mi = 0; mi < 2; mi++) {
                uint32_t addr = sA + rowA[mi] + (uint32_t)(((gA + kselA) ^ swA[mi]) << 4);
                LDSM_X4(aR[mi][0], aR[mi][1], aR[mi][2], aR[mi][3], addr);
            }
            uint32_t bR[8][2];
#pragma unroll
            for (int j = 0; j < 4; j++) {
                uint32_t addr = sB + rowB[j] + (uint32_t)(((gA + kselB) ^ swB[j]) << 4);
                LDSM_X4(bR[2 * j][0], bR[2 * j][1], bR[2 * j + 1][0], bR[2 * j + 1][1], addr);
            }
#pragma unroll
            for (int mi = 0; mi < 2; mi++)
#pragma unroll
                for (int ni = 0; ni < 8; ni++) {
                    asm volatile(
                        "mma.sync.aligned.m16n8k16.row.col.f32.f16.f16.f32 "
                        "{%0,%1,%2,%3}, {%4,%5,%6,%7}, {%8,%9}, {%0,%1,%2,%3};"
                        : "+f"(acc[mi][ni][0]), "+f"(acc[mi][ni][1]),
                          "+f"(acc[mi][ni][2]), "+f"(acc[mi][ni][3])
                        : "r"(aR[mi][0]), "r"(aR[mi][1]), "r"(aR[mi][2]), "r"(aR[mi][3]),
                          "r"(bR[ni][0]), "r"(bR[ni][1]));
                }
        }
    }

#pragma unroll
    for (int ni = 0; ni < 8; ni++) {
        int col = bn + wn * 64 + ni * 8 + 2 * tig;
        float bx = bias[col], by = bias[col + 1];
#pragma unroll
        for (int mi = 0; mi < 2; mi++) {
            int r0 = bm + wm * 32 + mi * 16 + gid;
            float ox0 = acc[mi][ni][0] + bx, oy0 = acc[mi][ni][1] + by;
            float ox1 = acc[mi][ni][2] + bx, oy1 = acc[mi][ni][3] + by;
            if (outH) {
                if (r0 < M)
                    *reinterpret_cast<__half2*>(outH + (size_t)r0 * DIM + col) =
                        __floats2half2_rn(ox0, oy0);
                if (r0 + 8 < M)
                    *reinterpret_cast<__half2*>(outH + (size_t)(r0 + 8) * DIM + col) =
                        __floats2half2_rn(ox1, oy1);
            } else {
                if (r0 < M)
                    *reinterpret_cast<float2*>(outF + (size_t)r0 * DIM + col) =
                        make_float2(ox0, oy0);
                if (r0 + 8 < M)
                    *reinterpret_cast<float2*>(outF + (size_t)(r0 + 8) * DIM + col) =
                        make_float2(ox1, oy1);
            }
        }
    }
}

// ---------------- L2 normalize + ReLU (fp16, ONE matrix; 512-thread blocks) ----------
__global__ void norm_relu1_kernel(__half* __restrict__ x, int n) {
    int row = blockIdx.x * (blockDim.x >> 5) + (threadIdx.x >> 5);
    if (row >= n) return;
    int lane = threadIdx.x & 31;
    uint4 v = reinterpret_cast<uint4*>(x + (size_t)row * DIM)[lane];
    __half2* h = reinterpret_cast<__half2*>(&v);
    float f[8];
    float s = 0.f;
#pragma unroll
    for (int j = 0; j < 4; j++) {
        float2 p = __half22float2(h[j]);
        f[j * 2] = p.x; f[j * 2 + 1] = p.y;
        s += p.x * p.x + p.y * p.y;
    }
#pragma unroll
    for (int o = 16; o; o >>= 1) s += __shfl_xor_sync(0xFFFFFFFFu, s, o);
    float inv = 1.0f / fmaxf(sqrtf(s), 1e-12f);
    uint4 ov;
    __half2* ho = reinterpret_cast<__half2*>(&ov);
#pragma unroll
    for (int j = 0; j < 4; j++)
        ho[j] = __floats2half2_rn(fmaxf(f[j * 2] * inv, 0.f), fmaxf(f[j * 2 + 1] * inv, 0.f));
    reinterpret_cast<uint4*>(x + (size_t)row * DIM)[lane] = ov;
}

// ---------------- host orchestration ----------------
extern "C" void kernel_launch(void* const* d_in, const int* in_sizes, int n_in,
                              void* d_out, int out_size) {
    (void)in_sizes; (void)n_in; (void)out_size;
    const float* xa_in = (const float*)d_in[0];
    const float* xp_in = (const float*)d_in[1];
    const float* Wl    = (const float*)d_in[2];
    const float* bl    = (const float*)d_in[3];
    const float* Wr    = (const float*)d_in[4];
    const int*   e_ap  = (const int*)d_in[5];
    const int*   e_pa  = (const int*)d_in[6];
    float* out = (float*)d_out;

    __half *xa16, *xp16, *bufA[2], *bufP[2], *aggA, *aggP, *hWl, *hWr;
    int *degA, *degP, *offA, *offP, *curA, *curP, *csrA, *csrP;
    cudaGetSymbolAddress((void**)&xa16, g_xa16);
    cudaGetSymbolAddress((void**)&xp16, g_xp16);
    cudaGetSymbolAddress((void**)&bufA[0], g_bufA0);
    cudaGetSymbolAddress((void**)&bufA[1], g_bufA1);
    cudaGetSymbolAddress((void**)&bufP[0], g_bufP0);
    cudaGetSymbolAddress((void**)&bufP[1], g_bufP1);
    cudaGetSymbolAddress((void**)&aggA, g_aggA);
    cudaGetSymbolAddress((void**)&aggP, g_aggP);
    cudaGetSymbolAddress((void**)&hWl, g_hWl);
    cudaGetSymbolAddress((void**)&hWr, g_hWr);
    cudaGetSymbolAddress((void**)&degA, g_degA);
    cudaGetSymbolAddress((void**)&degP, g_degP);
    cudaGetSymbolAddress((void**)&offA, g_offA);
    cudaGetSymbolAddress((void**)&offP, g_offP);
    cudaGetSymbolAddress((void**)&curA, g_curA);
    cudaGetSymbolAddress((void**)&curP, g_curP);
    cudaGetSymbolAddress((void**)&csrA, g_csrA);
    cudaGetSymbolAddress((void**)&csrP, g_csrP);

    static bool attr_set = false;
    if (!attr_set) {
        cudaFuncSetAttribute(gemm1_kernel, cudaFuncAttributeMaxDynamicSharedMemorySize,
                             6 * STG_H * (int)sizeof(__half));
        attr_set = true;
    }

    cudaStream_t sx = g_aux.s;

    cudaEventRecord(g_aux.fork, 0);
    cudaStreamWaitEvent(sx, g_aux.fork, 0);

    cvt_all_kernel<<<(N_NODES * DIM / 4 + 255) / 256, 256>>>(
        xa_in, xp_in, xa16, xp16, Wl, Wr, hWl, hWr,
        N_NODES * DIM / 4, W_ELEMS / 4);

    cudaMemsetAsync(degA, 0, N_NODES * sizeof(int), sx);
    cudaMemsetAsync(degP, 0, N_NODES * sizeof(int), sx);
    {
        dim3 g((N_EDGES + 255) / 256, 2);
        deg2_kernel<<<g, 256, 0, sx>>>(e_ap + N_EDGES, degP, e_pa + N_EDGES, degA, N_EDGES);
    }
    {
        dim3 g(SNB, 2);
        scan_p1<<<g, 256, 0, sx>>>(degP, degA, N_NODES);
        scan_p2<<<2, 128, 0, sx>>>(offP, offA, N_NODES);
        scan_p3<<<g, 256, 0, sx>>>(degP, degA, offP, curP, offA, curA, N_NODES);
    }
    {
        dim3 g((N_EDGES + 255) / 256, 2);
        fill2_kernel<<<g, 256, 0, sx>>>(e_ap, curP, csrP, e_pa, curA, csrA, N_EDGES);
    }

    cudaEventRecord(g_aux.join, sx);
    cudaStreamWaitEvent(0, g_aux.join, 0);

    const __half* inA = xa16;
    const __half* inP = xp16;

    dim3 gGrid(2, (N_NODES + 127) / 128);    // (2, 391) per direction
    int wBlocks = (N_NODES + 7) / 8;         // gather: 8 warps/block
    int nBlocks = (N_NODES + 15) / 16;       // norm: 16 warps/block
    const int smemBytes = 6 * STG_H * (int)sizeof(__half);   // 48KB

    for (int l = 0; l < N_LAYERS; l++) {
        const bool last = (l == N_LAYERS - 1);
        __half* outA = last ? nullptr : bufA[l & 1];
        __half* outP = last ? nullptr : bufP[l & 1];
        float* outA_f = last ? out : nullptr;
        float* outP_f = last ? out + (size_t)N_NODES * DIM : nullptr;

        const __half* wl_p = hWl + ((size_t)l * 2 + 0) * DIM * DIM;
        const __half* wr_p = hWr + ((size_t)l * 2 + 0) * DIM * DIM;
        const float*  bl_p = bl + ((size_t)l * 2 + 0) * DIM;
        const __half* wl_a = hWl + ((size_t)l * 2 + 1) * DIM * DIM;
        const __half* wr_a = hWr + ((size_t)l * 2 + 1) * DIM * DIM;
        const float*  bl_a = bl + ((size_t)l * 2 + 1) * DIM;

        cudaEventRecord(g_aux.fork, 0);
        cudaStreamWaitEvent(sx, g_aux.fork, 0);

        // chain P (default stream)
        gather1_kernel<<<wBlocks, 256>>>(inA, offP, csrP, aggP, N_NODES);
        gemm1_kernel<<<gGrid, 256, smemBytes>>>(aggP, inP, wl_p, wr_p, bl_p,
                                                outP, outP_f, N_NODES);
        if (!last) norm_relu1_kernel<<<nBlocks, 512>>>(outP, N_NODES);

        // chain A (aux stream)
        gather1_kernel<<<wBlocks, 256, 0, sx>>>(inP, offA, csrA, aggA, N_NODES);
        gemm1_kernel<<<gGrid, 256, smemBytes, sx>>>(aggA, inA, wl_a, wr_a, bl_a,
                                                    outA, outA_f, N_NODES);
        if (!last) norm_relu1_kernel<<<nBlocks, 512, 0, sx>>>(outA, N_NODES);

        cudaEventRecord(g_aux.join, sx);
        cudaStreamWaitEvent(0, g_aux.join, 0);

        inA = outA;
        inP = outP;
    }
}